// round 9
// baseline (speedup 1.0000x reference)
#include <cuda_runtime.h>
#include <cstdint>
#include <math.h>

#define BATCH 16
#define CH    512
#define NSP   1024
#define HEADS 4
#define HD    128
#define GROUPS_N 32
#define GSIZE (16*1024)
#define EPSV  1e-5f
#define ATT_SCALE 0.08838834764831845f

// ---------------------------------------------------------------------------
// Scratch (device globals). All GEMM operands stored pre-rounded to tf32.
// ---------------------------------------------------------------------------
__device__ float g_ht  [(size_t)BATCH*NSP*CH];
__device__ float g_qkvt[(size_t)BATCH*NSP*(3*CH)];
__device__ float g_vt  [(size_t)BATCH*HEADS*HD*NSP];
__device__ float g_ot  [(size_t)BATCH*NSP*CH];
__device__ float g_wq  [(size_t)(3*CH)*CH];
__device__ float g_wp  [(size_t)CH*CH];

// ---------------------------------------------------------------------------
// Helpers
// ---------------------------------------------------------------------------
__device__ __forceinline__ uint32_t smem_u32(const void* p){
    uint32_t a;
    asm("{ .reg .u64 t; cvta.to.shared.u64 t, %1; cvt.u32.u64 %0, t; }" : "=r"(a) : "l"(p));
    return a;
}
__device__ __forceinline__ uint32_t cvt_tf32(float f){
    uint32_t o; asm("cvt.rna.tf32.f32 %0, %1;" : "=r"(o) : "f"(f)); return o;
}
__device__ __forceinline__ float rnd_tf32(float f){ return __uint_as_float(cvt_tf32(f)); }

__device__ __forceinline__ void cp16(uint32_t dst, const float* src){
    asm volatile("cp.async.cg.shared.global [%0], [%1], 16;" :: "r"(dst), "l"(src) : "memory");
}
#define CP_COMMIT() asm volatile("cp.async.commit_group;" ::: "memory")
#define CP_WAIT1()  asm volatile("cp.async.wait_group 1;" ::: "memory")
#define CP_WAIT0()  asm volatile("cp.async.wait_group 0;" ::: "memory")

#define MMA8(c, a, b) \
    asm volatile("mma.sync.aligned.m16n8k8.row.col.f32.tf32.tf32.f32 " \
        "{%0,%1,%2,%3},{%4,%5,%6,%7},{%8,%9},{%0,%1,%2,%3};" \
        : "+f"((c)[0]), "+f"((c)[1]), "+f"((c)[2]), "+f"((c)[3]) \
        : "r"((a)[0]), "r"((a)[1]), "r"((a)[2]), "r"((a)[3]), \
          "r"((b)[0]), "r"((b)[1]))

// ---------------------------------------------------------------------------
// Weight pre-round
// ---------------------------------------------------------------------------
__global__ __launch_bounds__(256) void cvtw_kernel(
    const float* __restrict__ qw, const float* __restrict__ pw)
{
    int i = blockIdx.x * 256 + threadIdx.x;
    if (i < 3*CH*CH) g_wq[i] = rnd_tf32(qw[i]);
    if (i < CH*CH)   g_wp[i] = rnd_tf32(pw[i]);
}

// ---------------------------------------------------------------------------
// GroupNorm + transpose -> g_ht[b][n][c], tf32-rounded
// ---------------------------------------------------------------------------
__global__ __launch_bounds__(256) void gn_kernel(
    const float* __restrict__ x,
    const float* __restrict__ nw,
    const float* __restrict__ nb)
{
    __shared__ float t[16][257];
    int bg = blockIdx.x;
    int b = bg >> 5, g = bg & 31;
    const float* xp = x + (size_t)bg * GSIZE;
    int tid = threadIdx.x;

    float s = 0.f, s2 = 0.f;
    for (int i = tid; i < GSIZE; i += 256) { float v = xp[i]; s += v; s2 += v * v; }
    float* rs  = &t[0][0];
    float* rs2 = rs + 1024;
    rs[tid] = s; rs2[tid] = s2;
    __syncthreads();
    for (int o = 128; o > 0; o >>= 1) {
        if (tid < o) { rs[tid] += rs[tid + o]; rs2[tid] += rs2[tid + o]; }
        __syncthreads();
    }
    float mu   = rs[0] * (1.f / GSIZE);
    float var  = rs2[0] * (1.f / GSIZE) - mu * mu;
    float rinv = rsqrtf(var + EPSV);
    __syncthreads();

    int cl = tid & 15;
    float wc = nw[g * 16 + cl] * rinv;
    float bc = nb[g * 16 + cl] - mu * wc;
    float* hp = g_ht + (size_t)b * NSP * CH + g * 16;

    for (int n0 = 0; n0 < NSP; n0 += 256) {
#pragma unroll
        for (int c = 0; c < 16; c++) t[c][tid] = xp[c * NSP + n0 + tid];
        __syncthreads();
#pragma unroll
        for (int j = 0; j < 16; j++) {
            int nn = (tid >> 4) + j * 16;
            hp[(size_t)(n0 + nn) * CH + cl] = rnd_tf32(t[cl][nn] * wc + bc);
        }
        __syncthreads();
    }
}

// ---------------------------------------------------------------------------
// tf32 mma.sync GEMM (modes 0 and 3; attention is fused separately).
// 128 threads = 4 warps (2 x 2); warp tile 64x64; register double-buffered
// fragments; 2-stage cp.async pipeline (73.7 KB smem -> 3 CTAs/SM).
// ---------------------------------------------------------------------------
#define BK 32
#define ASTR 36
#define TILE_F (128*ASTR)
#define STAGE_F (2*TILE_F)
#define GEMM_SMEM (2*STAGE_F*4)   // 73728 bytes

template<int MODE>
__global__ __launch_bounds__(128, 3) void gemm_tc(
    const float* __restrict__ Wq, const float* __restrict__ Wp,
    const float* __restrict__ bias,
    const float* __restrict__ resid, float* __restrict__ outp)
{
    extern __shared__ float sm[];
    const int tid = threadIdx.x;
    uint32_t smb = smem_u32(sm);

    int m0 = blockIdx.x * 128;
    int n0 = blockIdx.y * 128;
    int z  = blockIdx.z;

    const float *A, *B;
    int lda, ldb, K;
    if (MODE == 0) {
        A = g_ht + ((size_t)z * NSP + m0) * CH; lda = CH;
        B = Wq + (size_t)n0 * CH;               ldb = CH;  K = CH;
    } else {
        A = g_ot + ((size_t)z * NSP + m0) * CH; lda = CH;
        B = Wp + (size_t)n0 * CH;               ldb = CH;  K = CH;
    }

    const int lane = tid & 31, wid = tid >> 5;
    const int wm = wid & 1, wn = wid >> 1;
    const int r_ = tid >> 3;
    const int f_ = tid & 7;

    float acc[4][8][4];
#pragma unroll
    for (int i = 0; i < 4; i++)
#pragma unroll
        for (int j = 0; j < 8; j++)
#pragma unroll
            for (int q = 0; q < 4; q++) acc[i][j][q] = 0.f;

    const int nch = K / BK;

    auto issue = [&](int ci) {
        int s = ci & 1;
        uint32_t as = smb + (uint32_t)(s * STAGE_F) * 4u;
        uint32_t bs = as + (uint32_t)TILE_F * 4u;
        int k0 = ci * BK;
#pragma unroll
        for (int t = 0; t < 8; t++) {
            int r = t * 16 + r_;
            cp16(as + (uint32_t)(r * ASTR + f_ * 4) * 4u, A + (size_t)r * lda + k0 + f_ * 4);
            cp16(bs + (uint32_t)(r * ASTR + f_ * 4) * 4u, B + (size_t)r * ldb + k0 + f_ * 4);
        }
    };

    issue(0); CP_COMMIT();

    const int rA = lane >> 2, kA = lane & 3;

    for (int ci = 0; ci < nch; ci++) {
        if (ci + 1 < nch) { issue(ci + 1); CP_COMMIT(); CP_WAIT1(); }
        else              { CP_WAIT0(); }
        __syncthreads();

        const float* As = sm + (ci & 1) * STAGE_F;
        const float* Bs = As + TILE_F;

        uint32_t a[2][4][4], b[2][8][2];
        {
            int kk = kA;
#pragma unroll
            for (int mt = 0; mt < 4; mt++) {
                int r = wm * 64 + mt * 16 + rA;
                a[0][mt][0] = __float_as_uint(As[r * ASTR + kk]);
                a[0][mt][1] = __float_as_uint(As[(r + 8) * ASTR + kk]);
                a[0][mt][2] = __float_as_uint(As[r * ASTR + kk + 4]);
                a[0][mt][3] = __float_as_uint(As[(r + 8) * ASTR + kk + 4]);
            }
#pragma unroll
            for (int nt = 0; nt < 8; nt++) {
                int n = wn * 64 + nt * 8 + rA;
                b[0][nt][0] = __float_as_uint(Bs[n * ASTR + kk]);
                b[0][nt][1] = __float_as_uint(Bs[n * ASTR + kk + 4]);
            }
        }

#pragma unroll
        for (int ks = 0; ks < 4; ks++) {
            int cur = ks & 1, nxt = cur ^ 1;
            if (ks < 3) {
                int kk = (ks + 1) * 8 + kA;
#pragma unroll
                for (int mt = 0; mt < 4; mt++) {
                    int r = wm * 64 + mt * 16 + rA;
                    a[nxt][mt][0] = __float_as_uint(As[r * ASTR + kk]);
                    a[nxt][mt][1] = __float_as_uint(As[(r + 8) * ASTR + kk]);
                    a[nxt][mt][2] = __float_as_uint(As[r * ASTR + kk + 4]);
                    a[nxt][mt][3] = __float_as_uint(As[(r + 8) * ASTR + kk + 4]);
                }
#pragma unroll
                for (int nt = 0; nt < 8; nt++) {
                    int n = wn * 64 + nt * 8 + rA;
                    b[nxt][nt][0] = __float_as_uint(Bs[n * ASTR + kk]);
                    b[nxt][nt][1] = __float_as_uint(Bs[n * ASTR + kk + 4]);
                }
            }
#pragma unroll
            for (int mt = 0; mt < 4; mt++)
#pragma unroll
                for (int nt = 0; nt < 8; nt++)
                    MMA8(acc[mt][nt], a[cur][mt], b[cur][nt]);
        }
        __syncthreads();
    }

    // Stage D through smem: Ds[col][row], stride 133
    float* Ds = sm;
#pragma unroll
    for (int mt = 0; mt < 4; mt++)
#pragma unroll
        for (int nt = 0; nt < 8; nt++) {
            int r = wm * 64 + mt * 16 + (lane >> 2);
            int c = wn * 64 + nt * 8 + (lane & 3) * 2;
            Ds[c * 133 + r]           = acc[mt][nt][0];
            Ds[(c + 1) * 133 + r]     = acc[mt][nt][1];
            Ds[c * 133 + r + 8]       = acc[mt][nt][2];
            Ds[(c + 1) * 133 + r + 8] = acc[mt][nt][3];
        }
    __syncthreads();

    if (MODE == 0) {
        if (n0 < 1024) {   // Q/K -> g_qkvt[b][n][o]
#pragma unroll 8
            for (int p = 0; p < 128; p++) {
                int e = p * 128 + tid; int r = e >> 7; int c = e & 127;
                g_qkvt[((size_t)z * NSP + m0 + r) * 1536 + n0 + c] = rnd_tf32(Ds[c * 133 + r] + bias[n0 + c]);
            }
        } else {           // V transposed -> g_vt[b,h][d][m]
            int h = (n0 - 1024) >> 7;
#pragma unroll 8
            for (int p = 0; p < 128; p++) {
                int e = p * 128 + tid; int c = e >> 7; int r = e & 127;
                g_vt[(((size_t)z * HEADS + h) * HD + c) * NSP + m0 + r] = rnd_tf32(Ds[c * 133 + r] + bias[n0 + c]);
            }
        }
    } else {               // MODE 3: bias + residual, transposed -> out
#pragma unroll 8
        for (int p = 0; p < 128; p++) {
            int e = p * 128 + tid; int c = e >> 7; int r = e & 127;
            size_t off = ((size_t)z * CH + n0 + c) * NSP + m0 + r;
            outp[off] = Ds[c * 133 + r] + bias[n0 + c] + resid[off];
        }
    }
}

// ---------------------------------------------------------------------------
// Fused flash attention (tf32 mma). CTA = 128 thr (4 warps), q-tile 64.
// Each warp owns 16 q-rows. Q lives in a DEDICATED smem buffer for the whole
// kernel (fragments re-read per k-tile, ks-outer loop) to keep registers
// below the spill threshold. Three smem buffers (8704 floats each):
//   bufQ: Q tile [64 q][128 d] stride 132 (persistent)
//   bufK: K tiles [64 keys][128 d] stride 132 (+ output staging at end)
//   bufV: V tiles [128 d][64 keys] stride 68
// Online softmax on mma accumulator layout; P remapped via quad shuffles.
// grid = (NSP/64, BATCH*HEADS)
// ---------------------------------------------------------------------------
#define FL_BUF 8704
#define FL_SMEM (3*FL_BUF*4)   // 104448 bytes

__global__ __launch_bounds__(128, 2) void flash_kernel()
{
    extern __shared__ float sm[];
    float* bufQ = sm;
    float* bufK = sm + FL_BUF;
    float* bufV = sm + 2 * FL_BUF;
    const int tid = threadIdx.x;
    uint32_t smb = smem_u32(sm);
    const int lane = tid & 31, wid = tid >> 5;
    const int g = lane >> 2, t = lane & 3;

    int n0 = blockIdx.x * 64;
    int bh = blockIdx.y;
    int b = bh >> 2, h = bh & 3;
    const float* qbase = g_qkvt + (size_t)b * NSP * 1536 + h * HD;
    const float* kbase = qbase + 512;
    const float* vbase = g_vt + (size_t)bh * HD * NSP;

    // Stage Q -> bufQ, K_0 -> bufK. Each tile = 64 rows x 128 floats =
    // 2048 float4 chunks; 16 chunks per thread.
    {
        uint32_t qs = smb;
        uint32_t ks = smb + FL_BUF * 4;
#pragma unroll
        for (int tr = 0; tr < 16; tr++) {
            int id = tr * 128 + tid; int r = id >> 5, f = id & 31;
            cp16(qs + (uint32_t)(r * 132 + f * 4) * 4u, qbase + (size_t)(n0 + r) * 1536 + f * 4);
            cp16(ks + (uint32_t)(r * 132 + f * 4) * 4u, kbase + (size_t)r * 1536 + f * 4);
        }
        CP_COMMIT();
    }

    float oacc[16][4];
#pragma unroll
    for (int i = 0; i < 16; i++)
#pragma unroll
        for (int q = 0; q < 4; q++) oacc[i][q] = 0.f;
    float rowm[2] = {-1e30f, -1e30f};
    float rowl[2] = {0.f, 0.f};

    const int qrow = wid * 16 + g;

    for (int it = 0; it < 16; it++) {
        CP_WAIT0();      // K_it (and, first iter, Q) resident
        __syncthreads();

        // prefetch V_it -> bufV ([128 d][64 keys], stride 68):
        // 128 x 64 floats = 2048 float4 chunks; 16 per thread.
        {
            uint32_t vs = smb + 2 * FL_BUF * 4;
#pragma unroll
            for (int tr = 0; tr < 16; tr++) {
                int id = tr * 128 + tid; int d = id >> 4, f = id & 15;
                cp16(vs + (uint32_t)(d * 68 + f * 4) * 4u,
                     vbase + (size_t)d * NSP + it * 64 + f * 4);
            }
            CP_COMMIT();
        }

        // S = Q K^T (warp: 16 q x 64 keys = 8 n8; ks-outer, Q frag reused
        // across the 8 nt MMAs)
        float sacc[8][4];
#pragma unroll
        for (int i = 0; i < 8; i++)
#pragma unroll
            for (int q = 0; q < 4; q++) sacc[i][q] = 0.f;

        const float* Ks = bufK;
        const float* Qs = bufQ;
#pragma unroll
        for (int ks = 0; ks < 16; ks++) {
            uint32_t qa[4];
            qa[0] = __float_as_uint(Qs[qrow * 132 + ks * 8 + t]);
            qa[1] = __float_as_uint(Qs[(qrow + 8) * 132 + ks * 8 + t]);
            qa[2] = __float_as_uint(Qs[qrow * 132 + ks * 8 + t + 4]);
            qa[3] = __float_as_uint(Qs[(qrow + 8) * 132 + ks * 8 + t + 4]);
#pragma unroll
            for (int nt = 0; nt < 8; nt++) {
                int n = nt * 8 + g;
                uint32_t bb[2];
                bb[0] = __float_as_uint(Ks[n * 132 + ks * 8 + t]);
                bb[1] = __float_as_uint(Ks[n * 132 + ks * 8 + t + 4]);
                MMA8(sacc[nt], qa, bb);
            }
        }

        // online softmax (rows: g -> idx 0, g+8 -> idx 1)
        float tm0 = -1e30f, tm1 = -1e30f;
#pragma unroll
        for (int nt = 0; nt < 8; nt++) {
            sacc[nt][0] *= ATT_SCALE; sacc[nt][1] *= ATT_SCALE;
            sacc[nt][2] *= ATT_SCALE; sacc[nt][3] *= ATT_SCALE;
            tm0 = fmaxf(tm0, fmaxf(sacc[nt][0], sacc[nt][1]));
            tm1 = fmaxf(tm1, fmaxf(sacc[nt][2], sacc[nt][3]));
        }
#pragma unroll
        for (int o = 1; o < 4; o <<= 1) {
            tm0 = fmaxf(tm0, __shfl_xor_sync(0xffffffffu, tm0, o));
            tm1 = fmaxf(tm1, __shfl_xor_sync(0xffffffffu, tm1, o));
        }
        float mn0 = fmaxf(rowm[0], tm0), mn1 = fmaxf(rowm[1], tm1);
        float al0 = __expf(rowm[0] - mn0), al1 = __expf(rowm[1] - mn1);
        float ts0 = 0.f, ts1 = 0.f;
#pragma unroll
        for (int nt = 0; nt < 8; nt++) {
            sacc[nt][0] = __expf(sacc[nt][0] - mn0);
            sacc[nt][1] = __expf(sacc[nt][1] - mn0);
            sacc[nt][2] = __expf(sacc[nt][2] - mn1);
            sacc[nt][3] = __expf(sacc[nt][3] - mn1);
            ts0 += sacc[nt][0] + sacc[nt][1];
            ts1 += sacc[nt][2] + sacc[nt][3];
        }
#pragma unroll
        for (int o = 1; o < 4; o <<= 1) {
            ts0 += __shfl_xor_sync(0xffffffffu, ts0, o);
            ts1 += __shfl_xor_sync(0xffffffffu, ts1, o);
        }
        rowl[0] = rowl[0] * al0 + ts0;
        rowl[1] = rowl[1] * al1 + ts1;
        rowm[0] = mn0; rowm[1] = mn1;
#pragma unroll
        for (int nt = 0; nt < 16; nt++) {
            oacc[nt][0] *= al0; oacc[nt][1] *= al0;
            oacc[nt][2] *= al1; oacc[nt][3] *= al1;
        }

        CP_WAIT0();      // V_it resident
        __syncthreads(); // also: all warps done reading K_it from bufK

        if (it < 15) {   // prefetch K_{it+1} -> bufK
            uint32_t ks = smb + FL_BUF * 4;
            const float* kb = kbase + (size_t)(it + 1) * 64 * 1536;
#pragma unroll
            for (int tr = 0; tr < 16; tr++) {
                int id = tr * 128 + tid; int r = id >> 5, f = id & 31;
                cp16(ks + (uint32_t)(r * 132 + f * 4) * 4u, kb + (size_t)r * 1536 + f * 4);
            }
            CP_COMMIT();
        }

        // O += P V^T  (P remapped from C-layout to A-fragment layout)
        const float* Vs = bufV;
        const int srcA = (lane & ~3) | (t >> 1);
        const int srcB = srcA + 2;
#pragma unroll
        for (int kt = 0; kt < 8; kt++) {
            float v0 = __shfl_sync(0xffffffffu, sacc[kt][0], srcA);
            float v1 = __shfl_sync(0xffffffffu, sacc[kt][1], srcA);
            float w0 = __shfl_sync(0xffffffffu, sacc[kt][0], srcB);
            float w1 = __shfl_sync(0xffffffffu, sacc[kt][1], srcB);
            float x0 = __shfl_sync(0xffffffffu, sacc[kt][2], srcA);
            float x1 = __shfl_sync(0xffffffffu, sacc[kt][3], srcA);
            float y0 = __shfl_sync(0xffffffffu, sacc[kt][2], srcB);
            float y1 = __shfl_sync(0xffffffffu, sacc[kt][3], srcB);
            uint32_t pa[4];
            pa[0] = cvt_tf32((t & 1) ? v1 : v0);
            pa[1] = cvt_tf32((t & 1) ? x1 : x0);
            pa[2] = cvt_tf32((t & 1) ? w1 : w0);
            pa[3] = cvt_tf32((t & 1) ? y1 : y0);
#pragma unroll
            for (int nt = 0; nt < 16; nt++) {
                int n = nt * 8 + g;
                uint32_t bb[2];
                bb[0] = __float_as_uint(Vs[n * 68 + kt * 8 + t]);
                bb[1] = __float_as_uint(Vs[n * 68 + kt * 8 + t + 4]);
                MMA8(oacc[nt], pa, bb);
            }
        }
    }

    // normalize, stage through bufK, write g_ot[b][q][h*128+d] (tf32-rounded)
    float inv0 = 1.f / rowl[0], inv1 = 1.f / rowl[1];
    __syncthreads();
    float* Os = bufK;
    {
        int r = qrow;
#pragma unroll
        for (int nt = 0; nt < 16; nt++) {
            int d = nt * 8 + 2 * t;
            Os[r * 132 + d]           = oacc[nt][0] * inv0;
            Os[r * 132 + d + 1]       = oacc[nt][1] * inv0;
            Os[(r + 8) * 132 + d]     = oacc[nt][2] * inv1;
            Os[(r + 8) * 132 + d + 1] = oacc[nt][3] * inv1;
        }
    }
    __syncthreads();
    // 64 rows x 128 floats = 2048 float4 chunks; 16 per thread.
#pragma unroll
    for (int tr = 0; tr < 16; tr++) {
        int id = tr * 128 + tid;
        int row = id >> 5, f = id & 31;
        float4 v = *(float4*)&Os[row * 132 + f * 4];
        v.x = rnd_tf32(v.x); v.y = rnd_tf32(v.y);
        v.z = rnd_tf32(v.z); v.w = rnd_tf32(v.w);
        *(float4*)&g_ot[((size_t)b * NSP + n0 + row) * CH + h * HD + f * 4] = v;
    }
}

// ---------------------------------------------------------------------------
// Launch
// ---------------------------------------------------------------------------
extern "C" void kernel_launch(void* const* d_in, const int* in_sizes, int n_in,
                              void* d_out, int out_size)
{
    const float* x      = (const float*)d_in[0];
    const float* norm_w = (const float*)d_in[1];
    const float* norm_b = (const float*)d_in[2];
    const float* qkv_w  = (const float*)d_in[3];
    const float* qkv_b  = (const float*)d_in[4];
    const float* proj_w = (const float*)d_in[5];
    const float* proj_b = (const float*)d_in[6];
    float* out = (float*)d_out;

    float* wq; cudaGetSymbolAddress((void**)&wq, g_wq);
    float* wp; cudaGetSymbolAddress((void**)&wp, g_wp);

    cudaFuncSetAttribute(gemm_tc<0>, cudaFuncAttributeMaxDynamicSharedMemorySize, GEMM_SMEM);
    cudaFuncSetAttribute(gemm_tc<3>, cudaFuncAttributeMaxDynamicSharedMemorySize, GEMM_SMEM);
    cudaFuncSetAttribute(flash_kernel, cudaFuncAttributeMaxDynamicSharedMemorySize, FL_SMEM);

    cvtw_kernel<<<(3 * CH * CH + 255) / 256, 256>>>(qkv_w, proj_w);
    gn_kernel<<<BATCH * GROUPS_N, 256>>>(x, norm_w, norm_b);

    gemm_tc<0><<<dim3(NSP / 128, 1536 / 128, BATCH), 128, GEMM_SMEM>>>(wq, nullptr, qkv_b, nullptr, nullptr);
    flash_kernel<<<dim3(NSP / 64, BATCH * HEADS), 128, FL_SMEM>>>();
    gemm_tc<3><<<dim3(NSP / 128, CH / 128, BATCH), 128, GEMM_SMEM>>>(nullptr, wp, proj_b, x, out);
}

// round 10
// speedup vs baseline: 1.3375x; 1.3375x over previous
#include <cuda_runtime.h>
#include <cuda_fp16.h>
#include <cstdint>
#include <math.h>

#define BATCH 16
#define CH    512
#define NSP   1024
#define HEADS 4
#define HD    128
#define GROUPS_N 32
#define GSIZE (16*1024)
#define EPSV  1e-5f
#define ATT_SCALE 0.08838834764831845f

// ---------------------------------------------------------------------------
// Scratch (device globals).
// ---------------------------------------------------------------------------
__device__ float  g_ht [(size_t)BATCH*NSP*CH];        // GN out [b][n][c], tf32-rounded
__device__ __half g_qkh[(size_t)BATCH*NSP*1024];      // Q(,scaled),K fp16 [b][n][o<1024]
__device__ __half g_vth[(size_t)BATCH*HEADS*HD*NSP];  // V fp16 [b,h][d][m]
__device__ float  g_ot [(size_t)BATCH*NSP*CH];        // attn out [b][n][c], tf32-rounded
__device__ float  g_wq [(size_t)(3*CH)*CH];           // tf32-rounded qkv_w
__device__ float  g_wp [(size_t)CH*CH];               // tf32-rounded proj_w

// ---------------------------------------------------------------------------
// Helpers
// ---------------------------------------------------------------------------
__device__ __forceinline__ uint32_t smem_u32(const void* p){
    uint32_t a;
    asm("{ .reg .u64 t; cvta.to.shared.u64 t, %1; cvt.u32.u64 %0, t; }" : "=r"(a) : "l"(p));
    return a;
}
__device__ __forceinline__ uint32_t cvt_tf32(float f){
    uint32_t o; asm("cvt.rna.tf32.f32 %0, %1;" : "=r"(o) : "f"(f)); return o;
}
__device__ __forceinline__ float rnd_tf32(float f){ return __uint_as_float(cvt_tf32(f)); }

__device__ __forceinline__ void cp16(uint32_t dst, const void* src){
    asm volatile("cp.async.cg.shared.global [%0], [%1], 16;" :: "r"(dst), "l"(src) : "memory");
}
#define CP_COMMIT() asm volatile("cp.async.commit_group;" ::: "memory")
#define CP_WAIT1()  asm volatile("cp.async.wait_group 1;" ::: "memory")
#define CP_WAIT0()  asm volatile("cp.async.wait_group 0;" ::: "memory")

// tf32 m16n8k8
#define MMA8(c, a, b) \
    asm volatile("mma.sync.aligned.m16n8k8.row.col.f32.tf32.tf32.f32 " \
        "{%0,%1,%2,%3},{%4,%5,%6,%7},{%8,%9},{%0,%1,%2,%3};" \
        : "+f"((c)[0]), "+f"((c)[1]), "+f"((c)[2]), "+f"((c)[3]) \
        : "r"((a)[0]), "r"((a)[1]), "r"((a)[2]), "r"((a)[3]), \
          "r"((b)[0]), "r"((b)[1]))

// fp16 m16n8k16, fp32 accum
#define MMAH(c, a, b) \
    asm volatile("mma.sync.aligned.m16n8k16.row.col.f32.f16.f16.f32 " \
        "{%0,%1,%2,%3},{%4,%5,%6,%7},{%8,%9},{%0,%1,%2,%3};" \
        : "+f"((c)[0]), "+f"((c)[1]), "+f"((c)[2]), "+f"((c)[3]) \
        : "r"((a)[0]), "r"((a)[1]), "r"((a)[2]), "r"((a)[3]), \
          "r"((b)[0]), "r"((b)[1]))

__device__ __forceinline__ uint32_t packh2(float lo, float hi){
    __half2 h = __floats2half2_rn(lo, hi);
    return *reinterpret_cast<uint32_t*>(&h);
}

// ---------------------------------------------------------------------------
// Weight pre-round
// ---------------------------------------------------------------------------
__global__ __launch_bounds__(256) void cvtw_kernel(
    const float* __restrict__ qw, const float* __restrict__ pw)
{
    int i = blockIdx.x * 256 + threadIdx.x;
    if (i < 3*CH*CH) g_wq[i] = rnd_tf32(qw[i]);
    if (i < CH*CH)   g_wp[i] = rnd_tf32(pw[i]);
}

// ---------------------------------------------------------------------------
// GroupNorm + transpose -> g_ht[b][n][c], tf32-rounded
// ---------------------------------------------------------------------------
__global__ __launch_bounds__(256) void gn_kernel(
    const float* __restrict__ x,
    const float* __restrict__ nw,
    const float* __restrict__ nb)
{
    __shared__ float t[16][257];
    int bg = blockIdx.x;
    int b = bg >> 5, g = bg & 31;
    const float* xp = x + (size_t)bg * GSIZE;
    int tid = threadIdx.x;

    float s = 0.f, s2 = 0.f;
    for (int i = tid; i < GSIZE; i += 256) { float v = xp[i]; s += v; s2 += v * v; }
    float* rs  = &t[0][0];
    float* rs2 = rs + 1024;
    rs[tid] = s; rs2[tid] = s2;
    __syncthreads();
    for (int o = 128; o > 0; o >>= 1) {
        if (tid < o) { rs[tid] += rs[tid + o]; rs2[tid] += rs2[tid + o]; }
        __syncthreads();
    }
    float mu   = rs[0] * (1.f / GSIZE);
    float var  = rs2[0] * (1.f / GSIZE) - mu * mu;
    float rinv = rsqrtf(var + EPSV);
    __syncthreads();

    int cl = tid & 15;
    float wc = nw[g * 16 + cl] * rinv;
    float bc = nb[g * 16 + cl] - mu * wc;
    float* hp = g_ht + (size_t)b * NSP * CH + g * 16;

    for (int n0 = 0; n0 < NSP; n0 += 256) {
#pragma unroll
        for (int c = 0; c < 16; c++) t[c][tid] = xp[c * NSP + n0 + tid];
        __syncthreads();
#pragma unroll
        for (int j = 0; j < 16; j++) {
            int nn = (tid >> 4) + j * 16;
            hp[(size_t)(n0 + nn) * CH + cl] = rnd_tf32(t[cl][nn] * wc + bc);
        }
        __syncthreads();
    }
}

// ---------------------------------------------------------------------------
// tf32 mma.sync GEMM (modes 0 and 3; attention is fused separately).
// 128 threads = 4 warps (2 x 2); warp tile 64x64; register double-buffered
// fragments; 2-stage cp.async pipeline (73.7 KB smem -> 3 CTAs/SM).
// MODE 0 epilogue: Q (scaled) / K -> g_qkh fp16; V transposed -> g_vth fp16.
// ---------------------------------------------------------------------------
#define BK 32
#define ASTR 36
#define TILE_F (128*ASTR)
#define STAGE_F (2*TILE_F)
#define GEMM_SMEM (2*STAGE_F*4)   // 73728 bytes

template<int MODE>
__global__ __launch_bounds__(128, 3) void gemm_tc(
    const float* __restrict__ Wq, const float* __restrict__ Wp,
    const float* __restrict__ bias,
    const float* __restrict__ resid, float* __restrict__ outp)
{
    extern __shared__ float sm[];
    const int tid = threadIdx.x;
    uint32_t smb = smem_u32(sm);

    int m0 = blockIdx.x * 128;
    int n0 = blockIdx.y * 128;
    int z  = blockIdx.z;

    const float *A, *B;
    int lda, ldb, K;
    if (MODE == 0) {
        A = g_ht + ((size_t)z * NSP + m0) * CH; lda = CH;
        B = Wq + (size_t)n0 * CH;               ldb = CH;  K = CH;
    } else {
        A = g_ot + ((size_t)z * NSP + m0) * CH; lda = CH;
        B = Wp + (size_t)n0 * CH;               ldb = CH;  K = CH;
    }

    const int lane = tid & 31, wid = tid >> 5;
    const int wm = wid & 1, wn = wid >> 1;
    const int r_ = tid >> 3;
    const int f_ = tid & 7;

    float acc[4][8][4];
#pragma unroll
    for (int i = 0; i < 4; i++)
#pragma unroll
        for (int j = 0; j < 8; j++)
#pragma unroll
            for (int q = 0; q < 4; q++) acc[i][j][q] = 0.f;

    const int nch = K / BK;

    auto issue = [&](int ci) {
        int s = ci & 1;
        uint32_t as = smb + (uint32_t)(s * STAGE_F) * 4u;
        uint32_t bs = as + (uint32_t)TILE_F * 4u;
        int k0 = ci * BK;
#pragma unroll
        for (int t = 0; t < 8; t++) {
            int r = t * 16 + r_;
            cp16(as + (uint32_t)(r * ASTR + f_ * 4) * 4u, A + (size_t)r * lda + k0 + f_ * 4);
            cp16(bs + (uint32_t)(r * ASTR + f_ * 4) * 4u, B + (size_t)r * ldb + k0 + f_ * 4);
        }
    };

    issue(0); CP_COMMIT();

    const int rA = lane >> 2, kA = lane & 3;

    for (int ci = 0; ci < nch; ci++) {
        if (ci + 1 < nch) { issue(ci + 1); CP_COMMIT(); CP_WAIT1(); }
        else              { CP_WAIT0(); }
        __syncthreads();

        const float* As = sm + (ci & 1) * STAGE_F;
        const float* Bs = As + TILE_F;

        uint32_t a[2][4][4], b[2][8][2];
        {
            int kk = kA;
#pragma unroll
            for (int mt = 0; mt < 4; mt++) {
                int r = wm * 64 + mt * 16 + rA;
                a[0][mt][0] = __float_as_uint(As[r * ASTR + kk]);
                a[0][mt][1] = __float_as_uint(As[(r + 8) * ASTR + kk]);
                a[0][mt][2] = __float_as_uint(As[r * ASTR + kk + 4]);
                a[0][mt][3] = __float_as_uint(As[(r + 8) * ASTR + kk + 4]);
            }
#pragma unroll
            for (int nt = 0; nt < 8; nt++) {
                int n = wn * 64 + nt * 8 + rA;
                b[0][nt][0] = __float_as_uint(Bs[n * ASTR + kk]);
                b[0][nt][1] = __float_as_uint(Bs[n * ASTR + kk + 4]);
            }
        }

#pragma unroll
        for (int ks = 0; ks < 4; ks++) {
            int cur = ks & 1, nxt = cur ^ 1;
            if (ks < 3) {
                int kk = (ks + 1) * 8 + kA;
#pragma unroll
                for (int mt = 0; mt < 4; mt++) {
                    int r = wm * 64 + mt * 16 + rA;
                    a[nxt][mt][0] = __float_as_uint(As[r * ASTR + kk]);
                    a[nxt][mt][1] = __float_as_uint(As[(r + 8) * ASTR + kk]);
                    a[nxt][mt][2] = __float_as_uint(As[r * ASTR + kk + 4]);
                    a[nxt][mt][3] = __float_as_uint(As[(r + 8) * ASTR + kk + 4]);
                }
#pragma unroll
                for (int nt = 0; nt < 8; nt++) {
                    int n = wn * 64 + nt * 8 + rA;
                    b[nxt][nt][0] = __float_as_uint(Bs[n * ASTR + kk]);
                    b[nxt][nt][1] = __float_as_uint(Bs[n * ASTR + kk + 4]);
                }
            }
#pragma unroll
            for (int mt = 0; mt < 4; mt++)
#pragma unroll
                for (int nt = 0; nt < 8; nt++)
                    MMA8(acc[mt][nt], a[cur][mt], b[cur][nt]);
        }
        __syncthreads();
    }

    // Stage D through smem: Ds[col][row], stride 133
    float* Ds = sm;
#pragma unroll
    for (int mt = 0; mt < 4; mt++)
#pragma unroll
        for (int nt = 0; nt < 8; nt++) {
            int r = wm * 64 + mt * 16 + (lane >> 2);
            int c = wn * 64 + nt * 8 + (lane & 3) * 2;
            Ds[c * 133 + r]           = acc[mt][nt][0];
            Ds[(c + 1) * 133 + r]     = acc[mt][nt][1];
            Ds[c * 133 + r + 8]       = acc[mt][nt][2];
            Ds[(c + 1) * 133 + r + 8] = acc[mt][nt][3];
        }
    __syncthreads();

    if (MODE == 0) {
        if (n0 < 1024) {   // Q (scaled) / K -> g_qkh fp16 [b][n][o]
            float sc = (n0 < 512) ? ATT_SCALE : 1.f;
#pragma unroll 8
            for (int p = 0; p < 128; p++) {
                int e = p * 128 + tid; int r = e >> 7; int c = e & 127;
                g_qkh[((size_t)z * NSP + m0 + r) * 1024 + n0 + c] =
                    __float2half_rn((Ds[c * 133 + r] + bias[n0 + c]) * sc);
            }
        } else {           // V transposed -> g_vth fp16 [b,h][d][m]
            int h = (n0 - 1024) >> 7;
#pragma unroll 8
            for (int p = 0; p < 128; p++) {
                int e = p * 128 + tid; int c = e >> 7; int r = e & 127;
                g_vth[(((size_t)z * HEADS + h) * HD + c) * NSP + m0 + r] =
                    __float2half_rn(Ds[c * 133 + r] + bias[n0 + c]);
            }
        }
    } else {               // MODE 3: bias + residual, transposed -> out
#pragma unroll 8
        for (int p = 0; p < 128; p++) {
            int e = p * 128 + tid; int c = e >> 7; int r = e & 127;
            size_t off = ((size_t)z * CH + n0 + c) * NSP + m0 + r;
            outp[off] = Ds[c * 133 + r] + bias[n0 + c] + resid[off];
        }
    }
}

// ---------------------------------------------------------------------------
// Fused flash attention, fp16 mma (m16n8k16, fp32 accum). CTA = 128 thr
// (4 warps), q-tile 64; each warp owns 16 q-rows. Q fragments persistent in
// registers (32 regs fp16). Streams 16 k-tiles of 64 keys.
// smem (halves): bufQ 64x136 @0, bufK 64x136 @8704, bufV 128x72 @17408.
// Strides 136/72 give conflict-free fragment LDS (bank = 4g + t).
// fp16 C-layout == A-layout: P feeds PV via register packs, no shuffles.
// grid = (NSP/64, BATCH*HEADS)
// ---------------------------------------------------------------------------
#define FLH_SMEM 53248

__global__ __launch_bounds__(128) void flash_kernel()
{
    extern __shared__ __half hsm[];
    __half* hQ = hsm;             // 64 x 136
    __half* hK = hsm + 8704;      // 64 x 136
    __half* hV = hsm + 17408;     // 128 x 72
    const int tid = threadIdx.x;
    uint32_t smb = smem_u32(hsm);
    const uint32_t kOff = 8704u * 2u, vOff = 17408u * 2u;
    const int lane = tid & 31, wid = tid >> 5;
    const int g = lane >> 2, t = lane & 3;

    int n0 = blockIdx.x * 64;
    int bh = blockIdx.y;
    int b = bh >> 2, h = bh & 3;
    const __half* qh = g_qkh + (size_t)b * NSP * 1024 + h * HD;
    const __half* kh = qh + 512;
    const __half* vh = g_vth + (size_t)bh * HD * NSP;

    // Stage Q -> bufQ, K_0 -> bufK. Tile = 64 rows x 128 halves = 16 KB =
    // 1024 16B-chunks; 8 per thread.
#pragma unroll
    for (int tr = 0; tr < 8; tr++) {
        int id = tr * 128 + tid; int r = id >> 4, f = id & 15;
        cp16(smb + (uint32_t)(r * 136 + f * 8) * 2u, qh + (size_t)(n0 + r) * 1024 + f * 8);
        cp16(smb + kOff + (uint32_t)(r * 136 + f * 8) * 2u, kh + (size_t)r * 1024 + f * 8);
    }
    CP_COMMIT();
    CP_WAIT0();
    __syncthreads();

    // Q fragments: 8 k16-steps x 4 regs (fp16x2), persistent
    uint32_t qf[8][4];
    {
        int r = wid * 16 + g;
#pragma unroll
        for (int ks = 0; ks < 8; ks++) {
            qf[ks][0] = *(const uint32_t*)&hQ[r * 136 + ks * 16 + 2 * t];
            qf[ks][1] = *(const uint32_t*)&hQ[(r + 8) * 136 + ks * 16 + 2 * t];
            qf[ks][2] = *(const uint32_t*)&hQ[r * 136 + ks * 16 + 2 * t + 8];
            qf[ks][3] = *(const uint32_t*)&hQ[(r + 8) * 136 + ks * 16 + 2 * t + 8];
        }
    }

    float oacc[16][4];
#pragma unroll
    for (int i = 0; i < 16; i++)
#pragma unroll
        for (int q = 0; q < 4; q++) oacc[i][q] = 0.f;
    float rowm[2] = {-1e30f, -1e30f};
    float rowl[2] = {0.f, 0.f};

    for (int it = 0; it < 16; it++) {
        CP_WAIT0();      // K_it resident (it=0: nothing outstanding)
        __syncthreads(); // K visible to all warps; bufV free (prev PV done)

        // prefetch V_it -> bufV: 128 d-rows x 64 halves (128B) = 1024 chunks
        {
#pragma unroll
            for (int tr = 0; tr < 8; tr++) {
                int id = tr * 128 + tid; int d = id >> 3, f = id & 7;
                cp16(smb + vOff + (uint32_t)(d * 72 + f * 8) * 2u,
                     vh + (size_t)d * NSP + it * 64 + f * 8);
            }
            CP_COMMIT();
        }

        // S = Q K^T : 8 n8-tiles x 8 k16-steps = 64 MMAs
        float sacc[8][4];
#pragma unroll
        for (int i = 0; i < 8; i++)
#pragma unroll
            for (int q = 0; q < 4; q++) sacc[i][q] = 0.f;

#pragma unroll
        for (int nt = 0; nt < 8; nt++) {
            int n = nt * 8 + g;
#pragma unroll
            for (int ks = 0; ks < 8; ks++) {
                uint32_t bb[2];
                bb[0] = *(const uint32_t*)&hK[n * 136 + ks * 16 + 2 * t];
                bb[1] = *(const uint32_t*)&hK[n * 136 + ks * 16 + 2 * t + 8];
                MMAH(sacc[nt], qf[ks], bb);
            }
        }

        // online softmax (scale already folded into Q)
        float tm0 = -1e30f, tm1 = -1e30f;
#pragma unroll
        for (int nt = 0; nt < 8; nt++) {
            tm0 = fmaxf(tm0, fmaxf(sacc[nt][0], sacc[nt][1]));
            tm1 = fmaxf(tm1, fmaxf(sacc[nt][2], sacc[nt][3]));
        }
#pragma unroll
        for (int o = 1; o < 4; o <<= 1) {
            tm0 = fmaxf(tm0, __shfl_xor_sync(0xffffffffu, tm0, o));
            tm1 = fmaxf(tm1, __shfl_xor_sync(0xffffffffu, tm1, o));
        }
        float mn0 = fmaxf(rowm[0], tm0), mn1 = fmaxf(rowm[1], tm1);
        float al0 = __expf(rowm[0] - mn0), al1 = __expf(rowm[1] - mn1);
        float ts0 = 0.f, ts1 = 0.f;
#pragma unroll
        for (int nt = 0; nt < 8; nt++) {
            sacc[nt][0] = __expf(sacc[nt][0] - mn0);
            sacc[nt][1] = __expf(sacc[nt][1] - mn0);
            sacc[nt][2] = __expf(sacc[nt][2] - mn1);
            sacc[nt][3] = __expf(sacc[nt][3] - mn1);
            ts0 += sacc[nt][0] + sacc[nt][1];
            ts1 += sacc[nt][2] + sacc[nt][3];
        }
#pragma unroll
        for (int o = 1; o < 4; o <<= 1) {
            ts0 += __shfl_xor_sync(0xffffffffu, ts0, o);
            ts1 += __shfl_xor_sync(0xffffffffu, ts1, o);
        }
        rowl[0] = rowl[0] * al0 + ts0;
        rowl[1] = rowl[1] * al1 + ts1;
        rowm[0] = mn0; rowm[1] = mn1;
#pragma unroll
        for (int nt = 0; nt < 16; nt++) {
            oacc[nt][0] *= al0; oacc[nt][1] *= al0;
            oacc[nt][2] *= al1; oacc[nt][3] *= al1;
        }

        CP_WAIT0();      // V_it resident
        __syncthreads(); // all warps done reading bufK

        if (it < 15) {   // prefetch K_{it+1} -> bufK
            const __half* kb = kh + (size_t)(it + 1) * 64 * 1024;
#pragma unroll
            for (int tr = 0; tr < 8; tr++) {
                int id = tr * 128 + tid; int r = id >> 4, f = id & 15;
                cp16(smb + kOff + (uint32_t)(r * 136 + f * 8) * 2u, kb + (size_t)r * 1024 + f * 8);
            }
            CP_COMMIT();
        }

        // O += P V^T : C-layout == A-layout, pack P in registers, no shuffles
#pragma unroll
        for (int kt = 0; kt < 4; kt++) {
            uint32_t pa[4];
            pa[0] = packh2(sacc[2 * kt][0],     sacc[2 * kt][1]);
            pa[1] = packh2(sacc[2 * kt][2],     sacc[2 * kt][3]);
            pa[2] = packh2(sacc[2 * kt + 1][0], sacc[2 * kt + 1][1]);
            pa[3] = packh2(sacc[2 * kt + 1][2], sacc[2 * kt + 1][3]);
#pragma unroll
            for (int nt = 0; nt < 16; nt++) {
                int d = nt * 8 + g;
                uint32_t bb[2];
                bb[0] = *(const uint32_t*)&hV[d * 72 + kt * 16 + 2 * t];
                bb[1] = *(const uint32_t*)&hV[d * 72 + kt * 16 + 2 * t + 8];
                MMAH(oacc[nt], pa, bb);
            }
        }
    }

    // normalize + direct global stores (float2 chunks, 32B per quad-group)
    float inv0 = 1.f / rowl[0], inv1 = 1.f / rowl[1];
    int r = wid * 16 + g;
    float* ob = g_ot + ((size_t)b * NSP + n0) * CH + h * HD;
#pragma unroll
    for (int nt = 0; nt < 16; nt++) {
        int d = nt * 8 + 2 * t;
        float2 v0, v1;
        v0.x = rnd_tf32(oacc[nt][0] * inv0); v0.y = rnd_tf32(oacc[nt][1] * inv0);
        v1.x = rnd_tf32(oacc[nt][2] * inv1); v1.y = rnd_tf32(oacc[nt][3] * inv1);
        *(float2*)&ob[(size_t)r * CH + d]       = v0;
        *(float2*)&ob[(size_t)(r + 8) * CH + d] = v1;
    }
}

// ---------------------------------------------------------------------------
// Launch
// ---------------------------------------------------------------------------
extern "C" void kernel_launch(void* const* d_in, const int* in_sizes, int n_in,
                              void* d_out, int out_size)
{
    const float* x      = (const float*)d_in[0];
    const float* norm_w = (const float*)d_in[1];
    const float* norm_b = (const float*)d_in[2];
    const float* qkv_w  = (const float*)d_in[3];
    const float* qkv_b  = (const float*)d_in[4];
    const float* proj_w = (const float*)d_in[5];
    const float* proj_b = (const float*)d_in[6];
    float* out = (float*)d_out;

    float* wq; cudaGetSymbolAddress((void**)&wq, g_wq);
    float* wp; cudaGetSymbolAddress((void**)&wp, g_wp);

    cudaFuncSetAttribute(gemm_tc<0>, cudaFuncAttributeMaxDynamicSharedMemorySize, GEMM_SMEM);
    cudaFuncSetAttribute(gemm_tc<3>, cudaFuncAttributeMaxDynamicSharedMemorySize, GEMM_SMEM);
    cudaFuncSetAttribute(flash_kernel, cudaFuncAttributeMaxDynamicSharedMemorySize, FLH_SMEM);

    cvtw_kernel<<<(3 * CH * CH + 255) / 256, 256>>>(qkv_w, proj_w);
    gn_kernel<<<BATCH * GROUPS_N, 256>>>(x, norm_w, norm_b);

    gemm_tc<0><<<dim3(NSP / 128, 1536 / 128, BATCH), 128, GEMM_SMEM>>>(wq, nullptr, qkv_b, nullptr, nullptr);
    flash_kernel<<<dim3(NSP / 64, BATCH * HEADS), 128, FLH_SMEM>>>();
    gemm_tc<3><<<dim3(NSP / 128, CH / 128, BATCH), 128, GEMM_SMEM>>>(nullptr, wp, proj_b, x, out);
}

// round 11
// speedup vs baseline: 1.8436x; 1.3784x over previous
#include <cuda_runtime.h>
#include <cuda_fp16.h>
#include <cstdint>
#include <math.h>

#define BATCH 16
#define CH    512
#define NSP   1024
#define HEADS 4
#define HD    128
#define GROUPS_N 32
#define GSIZE (16*1024)
#define EPSV  1e-5f
#define ATT_SCALE 0.08838834764831845f

// ---------------------------------------------------------------------------
// Scratch (device globals). fp16 operands everywhere; fp32 accumulation.
// ---------------------------------------------------------------------------
__device__ __half g_hth[(size_t)BATCH*NSP*CH];        // GN out [b][n][c]
__device__ __half g_qkh[(size_t)BATCH*NSP*1024];      // Q(scaled),K [b][n][o<1024]
__device__ __half g_vth[(size_t)BATCH*HEADS*HD*NSP];  // V [b,h][d][m]
__device__ __half g_oth[(size_t)BATCH*NSP*CH];        // attn out [b][n][c]
__device__ __half g_wqh[(size_t)(3*CH)*CH];           // fp16 qkv_w
__device__ __half g_wph[(size_t)CH*CH];               // fp16 proj_w

// ---------------------------------------------------------------------------
// Helpers
// ---------------------------------------------------------------------------
__device__ __forceinline__ uint32_t smem_u32(const void* p){
    uint32_t a;
    asm("{ .reg .u64 t; cvta.to.shared.u64 t, %1; cvt.u32.u64 %0, t; }" : "=r"(a) : "l"(p));
    return a;
}
__device__ __forceinline__ void cp16(uint32_t dst, const void* src){
    asm volatile("cp.async.cg.shared.global [%0], [%1], 16;" :: "r"(dst), "l"(src) : "memory");
}
#define CP_COMMIT() asm volatile("cp.async.commit_group;" ::: "memory")
#define CP_WAIT1()  asm volatile("cp.async.wait_group 1;" ::: "memory")
#define CP_WAIT0()  asm volatile("cp.async.wait_group 0;" ::: "memory")

// fp16 m16n8k16, fp32 accum
#define MMAH(c, a, b) \
    asm volatile("mma.sync.aligned.m16n8k16.row.col.f32.f16.f16.f32 " \
        "{%0,%1,%2,%3},{%4,%5,%6,%7},{%8,%9},{%0,%1,%2,%3};" \
        : "+f"((c)[0]), "+f"((c)[1]), "+f"((c)[2]), "+f"((c)[3]) \
        : "r"((a)[0]), "r"((a)[1]), "r"((a)[2]), "r"((a)[3]), \
          "r"((b)[0]), "r"((b)[1]))

__device__ __forceinline__ uint32_t packh2(float lo, float hi){
    __half2 h = __floats2half2_rn(lo, hi);
    return *reinterpret_cast<uint32_t*>(&h);
}

// ---------------------------------------------------------------------------
// Weight convert -> fp16
// ---------------------------------------------------------------------------
__global__ __launch_bounds__(256) void cvtw_kernel(
    const float* __restrict__ qw, const float* __restrict__ pw)
{
    int i = blockIdx.x * 256 + threadIdx.x;
    if (i < 3*CH*CH) g_wqh[i] = __float2half_rn(qw[i]);
    if (i < CH*CH)   g_wph[i] = __float2half_rn(pw[i]);
}

// ---------------------------------------------------------------------------
// GroupNorm + transpose -> g_hth[b][n][c] fp16
// ---------------------------------------------------------------------------
__global__ __launch_bounds__(256) void gn_kernel(
    const float* __restrict__ x,
    const float* __restrict__ nw,
    const float* __restrict__ nb)
{
    __shared__ float t[16][257];
    int bg = blockIdx.x;
    int b = bg >> 5, g = bg & 31;
    const float* xp = x + (size_t)bg * GSIZE;
    int tid = threadIdx.x;

    float s = 0.f, s2 = 0.f;
    for (int i = tid; i < GSIZE; i += 256) { float v = xp[i]; s += v; s2 += v * v; }
    float* rs  = &t[0][0];
    float* rs2 = rs + 1024;
    rs[tid] = s; rs2[tid] = s2;
    __syncthreads();
    for (int o = 128; o > 0; o >>= 1) {
        if (tid < o) { rs[tid] += rs[tid + o]; rs2[tid] += rs2[tid + o]; }
        __syncthreads();
    }
    float mu   = rs[0] * (1.f / GSIZE);
    float var  = rs2[0] * (1.f / GSIZE) - mu * mu;
    float rinv = rsqrtf(var + EPSV);
    __syncthreads();

    int cl = tid & 15;
    float wc = nw[g * 16 + cl] * rinv;
    float bc = nb[g * 16 + cl] - mu * wc;
    __half* hp = g_hth + (size_t)b * NSP * CH + g * 16;

    for (int n0 = 0; n0 < NSP; n0 += 256) {
#pragma unroll
        for (int c = 0; c < 16; c++) t[c][tid] = xp[c * NSP + n0 + tid];
        __syncthreads();
#pragma unroll
        for (int j = 0; j < 16; j++) {
            int nn = (tid >> 4) + j * 16;
            hp[(size_t)(n0 + nn) * CH + cl] = __float2half_rn(t[cl][nn] * wc + bc);
        }
        __syncthreads();
    }
}

// ---------------------------------------------------------------------------
// fp16 mma.sync GEMM: D[128m x 128n] = A[m][K] * B[n][K]^T (both K-major,
// fp16 in / fp32 accum). 128 threads = 4 warps (2x2); warp tile 64x64;
// BK=64 (4 k16 steps); register double-buffered fragments; 2-stage cp.async.
// smem/stage: 256 rows x 72 halves = 36 KB; 2 stages = 72 KB -> 3 CTAs/SM.
// MODE 0: A=g_hth, B=g_wqh, epi: +bias; Q(scaled)/K -> g_qkh; V -> g_vth^T
// MODE 3: A=g_oth, B=g_wph, epi: +bias +resid -> out fp32 (transposed)
// ---------------------------------------------------------------------------
#define BKH 64
#define HSTR 72
#define TILE_H (128*HSTR)          // halves per operand tile
#define STAGE_H (2*TILE_H)
#define GEMM_SMEM (2*STAGE_H*2)    // 73728 bytes

template<int MODE>
__global__ __launch_bounds__(128, 3) void gemm_tc(
    const float* __restrict__ bias,
    const float* __restrict__ resid, float* __restrict__ outp)
{
    extern __shared__ __half hsm[];
    const int tid = threadIdx.x;
    uint32_t smb = smem_u32(hsm);

    int m0 = blockIdx.x * 128;
    int n0 = blockIdx.y * 128;
    int z  = blockIdx.z;

    const __half *A, *B;
    int lda, ldb;
    if (MODE == 0) {
        A = g_hth + ((size_t)z * NSP + m0) * CH; lda = CH;
        B = g_wqh + (size_t)n0 * CH;             ldb = CH;
    } else {
        A = g_oth + ((size_t)z * NSP + m0) * CH; lda = CH;
        B = g_wph + (size_t)n0 * CH;             ldb = CH;
    }
    const int nch = CH / BKH;   // 8

    const int lane = tid & 31, wid = tid >> 5;
    const int wm = wid & 1, wn = wid >> 1;
    const int g = lane >> 2, t = lane & 3;
    const int rr = tid >> 3, f_ = tid & 7;

    float acc[4][8][4];
#pragma unroll
    for (int i = 0; i < 4; i++)
#pragma unroll
        for (int j = 0; j < 8; j++)
#pragma unroll
            for (int q = 0; q < 4; q++) acc[i][j][q] = 0.f;

    // loader: tile = 128 rows x 64 halves (128 B/row, 8 chunks); A then B
    auto issue = [&](int ci) {
        int s = ci & 1;
        uint32_t as = smb + (uint32_t)(s * STAGE_H) * 2u;
        uint32_t bs = as + (uint32_t)TILE_H * 2u;
        int k0 = ci * BKH;
#pragma unroll
        for (int it = 0; it < 8; it++) {
            int r = it * 16 + rr;
            cp16(as + (uint32_t)(r * HSTR + f_ * 8) * 2u, A + (size_t)r * lda + k0 + f_ * 8);
            cp16(bs + (uint32_t)(r * HSTR + f_ * 8) * 2u, B + (size_t)r * ldb + k0 + f_ * 8);
        }
    };

    issue(0); CP_COMMIT();

    for (int ci = 0; ci < nch; ci++) {
        if (ci + 1 < nch) { issue(ci + 1); CP_COMMIT(); CP_WAIT1(); }
        else              { CP_WAIT0(); }
        __syncthreads();

        const __half* As = hsm + (ci & 1) * STAGE_H;
        const __half* Bs = As + TILE_H;

        uint32_t a[2][4][4], b[2][8][2];
        {
#pragma unroll
            for (int mt = 0; mt < 4; mt++) {
                int r = wm * 64 + mt * 16 + g;
                a[0][mt][0] = *(const uint32_t*)&As[r * HSTR + 2 * t];
                a[0][mt][1] = *(const uint32_t*)&As[(r + 8) * HSTR + 2 * t];
                a[0][mt][2] = *(const uint32_t*)&As[r * HSTR + 2 * t + 8];
                a[0][mt][3] = *(const uint32_t*)&As[(r + 8) * HSTR + 2 * t + 8];
            }
#pragma unroll
            for (int nt = 0; nt < 8; nt++) {
                int n = wn * 64 + nt * 8 + g;
                b[0][nt][0] = *(const uint32_t*)&Bs[n * HSTR + 2 * t];
                b[0][nt][1] = *(const uint32_t*)&Bs[n * HSTR + 2 * t + 8];
            }
        }

#pragma unroll
        for (int ks = 0; ks < 4; ks++) {
            int cur = ks & 1, nxt = cur ^ 1;
            if (ks < 3) {
                int kk = (ks + 1) * 16;
#pragma unroll
                for (int mt = 0; mt < 4; mt++) {
                    int r = wm * 64 + mt * 16 + g;
                    a[nxt][mt][0] = *(const uint32_t*)&As[r * HSTR + kk + 2 * t];
                    a[nxt][mt][1] = *(const uint32_t*)&As[(r + 8) * HSTR + kk + 2 * t];
                    a[nxt][mt][2] = *(const uint32_t*)&As[r * HSTR + kk + 2 * t + 8];
                    a[nxt][mt][3] = *(const uint32_t*)&As[(r + 8) * HSTR + kk + 2 * t + 8];
                }
#pragma unroll
                for (int nt = 0; nt < 8; nt++) {
                    int n = wn * 64 + nt * 8 + g;
                    b[nxt][nt][0] = *(const uint32_t*)&Bs[n * HSTR + kk + 2 * t];
                    b[nxt][nt][1] = *(const uint32_t*)&Bs[n * HSTR + kk + 2 * t + 8];
                }
            }
#pragma unroll
            for (int mt = 0; mt < 4; mt++)
#pragma unroll
                for (int nt = 0; nt < 8; nt++)
                    MMAH(acc[mt][nt], a[cur][mt], b[cur][nt]);
        }
        __syncthreads();
    }

    // Stage D through smem (fp32 view): Ds[col][row], stride 133
    float* Ds = (float*)hsm;
#pragma unroll
    for (int mt = 0; mt < 4; mt++)
#pragma unroll
        for (int nt = 0; nt < 8; nt++) {
            int r = wm * 64 + mt * 16 + g;
            int c = wn * 64 + nt * 8 + 2 * t;
            Ds[c * 133 + r]           = acc[mt][nt][0];
            Ds[(c + 1) * 133 + r]     = acc[mt][nt][1];
            Ds[c * 133 + r + 8]       = acc[mt][nt][2];
            Ds[(c + 1) * 133 + r + 8] = acc[mt][nt][3];
        }
    __syncthreads();

    if (MODE == 0) {
        if (n0 < 1024) {   // Q (scaled) / K -> g_qkh fp16 [b][n][o]
            float sc = (n0 < 512) ? ATT_SCALE : 1.f;
#pragma unroll 8
            for (int p = 0; p < 128; p++) {
                int e = p * 128 + tid; int r = e >> 7; int c = e & 127;
                g_qkh[((size_t)z * NSP + m0 + r) * 1024 + n0 + c] =
                    __float2half_rn((Ds[c * 133 + r] + bias[n0 + c]) * sc);
            }
        } else {           // V transposed -> g_vth fp16 [b,h][d][m]
            int h = (n0 - 1024) >> 7;
#pragma unroll 8
            for (int p = 0; p < 128; p++) {
                int e = p * 128 + tid; int c = e >> 7; int r = e & 127;
                g_vth[(((size_t)z * HEADS + h) * HD + c) * NSP + m0 + r] =
                    __float2half_rn(Ds[c * 133 + r] + bias[n0 + c]);
            }
        }
    } else {               // MODE 3: bias + residual, transposed -> out fp32
#pragma unroll 8
        for (int p = 0; p < 128; p++) {
            int e = p * 128 + tid; int c = e >> 7; int r = e & 127;
            size_t off = ((size_t)z * CH + n0 + c) * NSP + m0 + r;
            outp[off] = Ds[c * 133 + r] + bias[n0 + c] + resid[off];
        }
    }
}

// ---------------------------------------------------------------------------
// Fused flash attention, fp16 mma (m16n8k16, fp32 accum). CTA = 128 thr
// (4 warps), q-tile 64; each warp owns 16 q-rows. Q fragments persistent in
// registers. Streams 16 k-tiles of 64 keys.
// smem (halves): bufQ 64x136 @0, bufK 64x136 @8704, bufV 128x72 @17408.
// fp16 C-layout == A-layout: P feeds PV via register packs, no shuffles.
// Output written fp16 -> g_oth. grid = (NSP/64, BATCH*HEADS)
// ---------------------------------------------------------------------------
#define FLH_SMEM 53248

__global__ __launch_bounds__(128, 3) void flash_kernel()
{
    extern __shared__ __half hsm[];
    __half* hQ = hsm;             // 64 x 136
    __half* hK = hsm + 8704;      // 64 x 136
    __half* hV = hsm + 17408;     // 128 x 72
    const int tid = threadIdx.x;
    uint32_t smb = smem_u32(hsm);
    const uint32_t kOff = 8704u * 2u, vOff = 17408u * 2u;
    const int lane = tid & 31, wid = tid >> 5;
    const int g = lane >> 2, t = lane & 3;

    int n0 = blockIdx.x * 64;
    int bh = blockIdx.y;
    int b = bh >> 2, h = bh & 3;
    const __half* qh = g_qkh + (size_t)b * NSP * 1024 + h * HD;
    const __half* kh = qh + 512;
    const __half* vh = g_vth + (size_t)bh * HD * NSP;

    // Stage Q -> bufQ, K_0 -> bufK. Tile = 64 rows x 128 halves = 1024 chunks.
#pragma unroll
    for (int tr = 0; tr < 8; tr++) {
        int id = tr * 128 + tid; int r = id >> 4, f = id & 15;
        cp16(smb + (uint32_t)(r * 136 + f * 8) * 2u, qh + (size_t)(n0 + r) * 1024 + f * 8);
        cp16(smb + kOff + (uint32_t)(r * 136 + f * 8) * 2u, kh + (size_t)r * 1024 + f * 8);
    }
    CP_COMMIT();
    CP_WAIT0();
    __syncthreads();

    // Q fragments: 8 k16-steps x 4 regs (fp16x2), persistent
    uint32_t qf[8][4];
    {
        int r = wid * 16 + g;
#pragma unroll
        for (int ks = 0; ks < 8; ks++) {
            qf[ks][0] = *(const uint32_t*)&hQ[r * 136 + ks * 16 + 2 * t];
            qf[ks][1] = *(const uint32_t*)&hQ[(r + 8) * 136 + ks * 16 + 2 * t];
            qf[ks][2] = *(const uint32_t*)&hQ[r * 136 + ks * 16 + 2 * t + 8];
            qf[ks][3] = *(const uint32_t*)&hQ[(r + 8) * 136 + ks * 16 + 2 * t + 8];
        }
    }

    float oacc[16][4];
#pragma unroll
    for (int i = 0; i < 16; i++)
#pragma unroll
        for (int q = 0; q < 4; q++) oacc[i][q] = 0.f;
    float rowm[2] = {-1e30f, -1e30f};
    float rowl[2] = {0.f, 0.f};

    for (int it = 0; it < 16; it++) {
        CP_WAIT0();      // K_it resident
        __syncthreads(); // K visible; bufV free (prev PV done)

        // prefetch V_it -> bufV: 128 d-rows x 64 halves = 1024 chunks
        {
#pragma unroll
            for (int tr = 0; tr < 8; tr++) {
                int id = tr * 128 + tid; int d = id >> 3, f = id & 7;
                cp16(smb + vOff + (uint32_t)(d * 72 + f * 8) * 2u,
                     vh + (size_t)d * NSP + it * 64 + f * 8);
            }
            CP_COMMIT();
        }

        // S = Q K^T : 8 n8-tiles x 8 k16-steps
        float sacc[8][4];
#pragma unroll
        for (int i = 0; i < 8; i++)
#pragma unroll
            for (int q = 0; q < 4; q++) sacc[i][q] = 0.f;

#pragma unroll
        for (int nt = 0; nt < 8; nt++) {
            int n = nt * 8 + g;
#pragma unroll
            for (int ks = 0; ks < 8; ks++) {
                uint32_t bb[2];
                bb[0] = *(const uint32_t*)&hK[n * 136 + ks * 16 + 2 * t];
                bb[1] = *(const uint32_t*)&hK[n * 136 + ks * 16 + 2 * t + 8];
                MMAH(sacc[nt], qf[ks], bb);
            }
        }

        // online softmax (scale folded into Q)
        float tm0 = -1e30f, tm1 = -1e30f;
#pragma unroll
        for (int nt = 0; nt < 8; nt++) {
            tm0 = fmaxf(tm0, fmaxf(sacc[nt][0], sacc[nt][1]));
            tm1 = fmaxf(tm1, fmaxf(sacc[nt][2], sacc[nt][3]));
        }
#pragma unroll
        for (int o = 1; o < 4; o <<= 1) {
            tm0 = fmaxf(tm0, __shfl_xor_sync(0xffffffffu, tm0, o));
            tm1 = fmaxf(tm1, __shfl_xor_sync(0xffffffffu, tm1, o));
        }
        float mn0 = fmaxf(rowm[0], tm0), mn1 = fmaxf(rowm[1], tm1);
        float al0 = __expf(rowm[0] - mn0), al1 = __expf(rowm[1] - mn1);
        float ts0 = 0.f, ts1 = 0.f;
#pragma unroll
        for (int nt = 0; nt < 8; nt++) {
            sacc[nt][0] = __expf(sacc[nt][0] - mn0);
            sacc[nt][1] = __expf(sacc[nt][1] - mn0);
            sacc[nt][2] = __expf(sacc[nt][2] - mn1);
            sacc[nt][3] = __expf(sacc[nt][3] - mn1);
            ts0 += sacc[nt][0] + sacc[nt][1];
            ts1 += sacc[nt][2] + sacc[nt][3];
        }
#pragma unroll
        for (int o = 1; o < 4; o <<= 1) {
            ts0 += __shfl_xor_sync(0xffffffffu, ts0, o);
            ts1 += __shfl_xor_sync(0xffffffffu, ts1, o);
        }
        rowl[0] = rowl[0] * al0 + ts0;
        rowl[1] = rowl[1] * al1 + ts1;
        rowm[0] = mn0; rowm[1] = mn1;
#pragma unroll
        for (int nt = 0; nt < 16; nt++) {
            oacc[nt][0] *= al0; oacc[nt][1] *= al0;
            oacc[nt][2] *= al1; oacc[nt][3] *= al1;
        }

        CP_WAIT0();      // V_it resident
        __syncthreads(); // all warps done reading bufK

        if (it < 15) {   // prefetch K_{it+1} -> bufK
            const __half* kb = kh + (size_t)(it + 1) * 64 * 1024;
#pragma unroll
            for (int tr = 0; tr < 8; tr++) {
                int id = tr * 128 + tid; int r = id >> 4, f = id & 15;
                cp16(smb + kOff + (uint32_t)(r * 136 + f * 8) * 2u, kb + (size_t)r * 1024 + f * 8);
            }
            CP_COMMIT();
        }

        // O += P V^T : C-layout == A-layout, pack P in registers
#pragma unroll
        for (int kt = 0; kt < 4; kt++) {
            uint32_t pa[4];
            pa[0] = packh2(sacc[2 * kt][0],     sacc[2 * kt][1]);
            pa[1] = packh2(sacc[2 * kt][2],     sacc[2 * kt][3]);
            pa[2] = packh2(sacc[2 * kt + 1][0], sacc[2 * kt + 1][1]);
            pa[3] = packh2(sacc[2 * kt + 1][2], sacc[2 * kt + 1][3]);
#pragma unroll
            for (int nt = 0; nt < 16; nt++) {
                int d = nt * 8 + g;
                uint32_t bb[2];
                bb[0] = *(const uint32_t*)&hV[d * 72 + kt * 16 + 2 * t];
                bb[1] = *(const uint32_t*)&hV[d * 72 + kt * 16 + 2 * t + 8];
                MMAH(oacc[nt], pa, bb);
            }
        }
    }

    // normalize + direct fp16 stores (4B h2 chunks) -> g_oth[b][n][c]
    float inv0 = 1.f / rowl[0], inv1 = 1.f / rowl[1];
    int r = wid * 16 + g;
    __half* ob = g_oth + ((size_t)b * NSP + n0) * CH + h * HD;
#pragma unroll
    for (int nt = 0; nt < 16; nt++) {
        int d = nt * 8 + 2 * t;
        *(uint32_t*)&ob[(size_t)r * CH + d] =
            packh2(oacc[nt][0] * inv0, oacc[nt][1] * inv0);
        *(uint32_t*)&ob[(size_t)(r + 8) * CH + d] =
            packh2(oacc[nt][2] * inv1, oacc[nt][3] * inv1);
    }
}

// ---------------------------------------------------------------------------
// Launch
// ---------------------------------------------------------------------------
extern "C" void kernel_launch(void* const* d_in, const int* in_sizes, int n_in,
                              void* d_out, int out_size)
{
    const float* x      = (const float*)d_in[0];
    const float* norm_w = (const float*)d_in[1];
    const float* norm_b = (const float*)d_in[2];
    const float* qkv_w  = (const float*)d_in[3];
    const float* qkv_b  = (const float*)d_in[4];
    const float* proj_w = (const float*)d_in[5];
    const float* proj_b = (const float*)d_in[6];
    float* out = (float*)d_out;

    cudaFuncSetAttribute(gemm_tc<0>, cudaFuncAttributeMaxDynamicSharedMemorySize, GEMM_SMEM);
    cudaFuncSetAttribute(gemm_tc<3>, cudaFuncAttributeMaxDynamicSharedMemorySize, GEMM_SMEM);
    cudaFuncSetAttribute(flash_kernel, cudaFuncAttributeMaxDynamicSharedMemorySize, FLH_SMEM);

    cvtw_kernel<<<(3 * CH * CH + 255) / 256, 256>>>(qkv_w, proj_w);
    gn_kernel<<<BATCH * GROUPS_N, 256>>>(x, norm_w, norm_b);

    gemm_tc<0><<<dim3(NSP / 128, 1536 / 128, BATCH), 128, GEMM_SMEM>>>(qkv_b, nullptr, nullptr);
    flash_kernel<<<dim3(NSP / 64, BATCH * HEADS), 128, FLH_SMEM>>>();
    gemm_tc<3><<<dim3(NSP / 128, CH / 128, BATCH), 128, GEMM_SMEM>>>(proj_b, x, out);
}

// round 12
// speedup vs baseline: 1.9160x; 1.0393x over previous
#include <cuda_runtime.h>
#include <cuda_fp16.h>
#include <cstdint>
#include <math.h>

#define BATCH 16
#define CH    512
#define NSP   1024
#define HEADS 4
#define HD    128
#define GROUPS_N 32
#define GSIZE (16*1024)
#define EPSV  1e-5f
#define ATT_SCALE 0.08838834764831845f
// ATT_SCALE * log2(e): Q pre-scale so softmax uses exp2
#define QSC_L2E 0.12751741204555613f

// ---------------------------------------------------------------------------
// Scratch (device globals). fp16 operands; fp32 accumulation.
// ---------------------------------------------------------------------------
__device__ __half g_hth[(size_t)BATCH*NSP*CH];        // GN out [b][n][c]
__device__ __half g_qkh[(size_t)BATCH*NSP*1024];      // Q(scaled),K [b][n][o<1024]
__device__ __half g_vth[(size_t)BATCH*HEADS*HD*NSP];  // V [b,h][d][m]
__device__ __half g_oth[(size_t)BATCH*NSP*CH];        // attn out [b][n][c]
__device__ __half g_wqh[(size_t)(3*CH)*CH];           // fp16 qkv_w
__device__ __half g_wph[(size_t)CH*CH];               // fp16 proj_w

// ---------------------------------------------------------------------------
// Helpers
// ---------------------------------------------------------------------------
__device__ __forceinline__ uint32_t smem_u32(const void* p){
    uint32_t a;
    asm("{ .reg .u64 t; cvta.to.shared.u64 t, %1; cvt.u32.u64 %0, t; }" : "=r"(a) : "l"(p));
    return a;
}
__device__ __forceinline__ void cp16(uint32_t dst, const void* src){
    asm volatile("cp.async.cg.shared.global [%0], [%1], 16;" :: "r"(dst), "l"(src) : "memory");
}
#define CP_COMMIT() asm volatile("cp.async.commit_group;" ::: "memory")
#define CP_WAIT1()  asm volatile("cp.async.wait_group 1;" ::: "memory")
#define CP_WAIT0()  asm volatile("cp.async.wait_group 0;" ::: "memory")

#define MMAH(c, a, b) \
    asm volatile("mma.sync.aligned.m16n8k16.row.col.f32.f16.f16.f32 " \
        "{%0,%1,%2,%3},{%4,%5,%6,%7},{%8,%9},{%0,%1,%2,%3};" \
        : "+f"((c)[0]), "+f"((c)[1]), "+f"((c)[2]), "+f"((c)[3]) \
        : "r"((a)[0]), "r"((a)[1]), "r"((a)[2]), "r"((a)[3]), \
          "r"((b)[0]), "r"((b)[1]))

#define LDSM4(r0, r1, r2, r3, addr) \
    asm volatile("ldmatrix.sync.aligned.m8n8.x4.shared.b16 {%0,%1,%2,%3}, [%4];" \
        : "=r"(r0), "=r"(r1), "=r"(r2), "=r"(r3) : "r"(addr))

__device__ __forceinline__ uint32_t packh2(float lo, float hi){
    __half2 h = __floats2half2_rn(lo, hi);
    return *reinterpret_cast<uint32_t*>(&h);
}

// ---------------------------------------------------------------------------
// Weight convert -> fp16
// ---------------------------------------------------------------------------
__global__ __launch_bounds__(256) void cvtw_kernel(
    const float* __restrict__ qw, const float* __restrict__ pw)
{
    int i = blockIdx.x * 256 + threadIdx.x;
    if (i < 3*CH*CH) g_wqh[i] = __float2half_rn(qw[i]);
    if (i < CH*CH)   g_wph[i] = __float2half_rn(pw[i]);
}

// ---------------------------------------------------------------------------
// GroupNorm + transpose -> g_hth[b][n][c] fp16
// ---------------------------------------------------------------------------
__global__ __launch_bounds__(256) void gn_kernel(
    const float* __restrict__ x,
    const float* __restrict__ nw,
    const float* __restrict__ nb)
{
    __shared__ float t[16][257];
    int bg = blockIdx.x;
    int b = bg >> 5, g = bg & 31;
    const float* xp = x + (size_t)bg * GSIZE;
    int tid = threadIdx.x;

    float s = 0.f, s2 = 0.f;
    for (int i = tid; i < GSIZE; i += 256) { float v = xp[i]; s += v; s2 += v * v; }
    float* rs  = &t[0][0];
    float* rs2 = rs + 1024;
    rs[tid] = s; rs2[tid] = s2;
    __syncthreads();
    for (int o = 128; o > 0; o >>= 1) {
        if (tid < o) { rs[tid] += rs[tid + o]; rs2[tid] += rs2[tid + o]; }
        __syncthreads();
    }
    float mu   = rs[0] * (1.f / GSIZE);
    float var  = rs2[0] * (1.f / GSIZE) - mu * mu;
    float rinv = rsqrtf(var + EPSV);
    __syncthreads();

    int cl = tid & 15;
    float wc = nw[g * 16 + cl] * rinv;
    float bc = nb[g * 16 + cl] - mu * wc;
    __half* hp = g_hth + (size_t)b * NSP * CH + g * 16;

    for (int n0 = 0; n0 < NSP; n0 += 256) {
#pragma unroll
        for (int c = 0; c < 16; c++) t[c][tid] = xp[c * NSP + n0 + tid];
        __syncthreads();
#pragma unroll
        for (int j = 0; j < 16; j++) {
            int nn = (tid >> 4) + j * 16;
            hp[(size_t)(n0 + nn) * CH + cl] = __float2half_rn(t[cl][nn] * wc + bc);
        }
        __syncthreads();
    }
}

// ---------------------------------------------------------------------------
// fp16 mma.sync GEMM with ldmatrix fragment loads.
// 128 threads = 4 warps (2x2); warp tile 64x64; BK=64 (4 k16 steps);
// register double-buffered fragments; 2-stage cp.async; 72 KB smem -> 3 CTA/SM.
// MODE 0: A=g_hth, B=g_wqh; epi: +bias; Q(scaled*log2e)/K -> g_qkh; V -> g_vth^T
// MODE 3: A=g_oth, B=g_wph; epi: +bias +resid -> out fp32 (transposed)
// ---------------------------------------------------------------------------
#define BKH 64
#define HSTR 72
#define HSTRB (HSTR*2)             // 144 bytes
#define TILE_H (128*HSTR)
#define STAGE_H (2*TILE_H)
#define GEMM_SMEM (2*STAGE_H*2)    // 73728 bytes

template<int MODE>
__global__ __launch_bounds__(128, 3) void gemm_tc(
    const float* __restrict__ bias,
    const float* __restrict__ resid, float* __restrict__ outp)
{
    extern __shared__ __half hsm[];
    const int tid = threadIdx.x;
    uint32_t smb = smem_u32(hsm);

    int m0 = blockIdx.x * 128;
    int n0 = blockIdx.y * 128;
    int z  = blockIdx.z;

    const __half *A, *B;
    if (MODE == 0) {
        A = g_hth + ((size_t)z * NSP + m0) * CH;
        B = g_wqh + (size_t)n0 * CH;
    } else {
        A = g_oth + ((size_t)z * NSP + m0) * CH;
        B = g_wph + (size_t)n0 * CH;
    }
    const int lda = CH, ldb = CH;
    const int nch = CH / BKH;   // 8

    const int lane = tid & 31, wid = tid >> 5;
    const int wm = wid & 1, wn = wid >> 1;
    const int g = lane >> 2, t = lane & 3;
    const int rr = tid >> 3, f_ = tid & 7;

    // ldmatrix per-lane byte offsets (stride 144B)
    const uint32_t ldA = (uint32_t)(((lane & 7) + ((lane >> 3) & 1) * 8) * HSTRB + (lane >> 4) * 16);
    const uint32_t ldB = (uint32_t)((lane & 7) * HSTRB + ((lane >> 3) & 1) * 16 + (lane >> 4) * 8 * HSTRB);

    float acc[4][8][4];
#pragma unroll
    for (int i = 0; i < 4; i++)
#pragma unroll
        for (int j = 0; j < 8; j++)
#pragma unroll
            for (int q = 0; q < 4; q++) acc[i][j][q] = 0.f;

    auto issue = [&](int ci) {
        int s = ci & 1;
        uint32_t as = smb + (uint32_t)(s * STAGE_H) * 2u;
        uint32_t bs = as + (uint32_t)TILE_H * 2u;
        int k0 = ci * BKH;
#pragma unroll
        for (int it = 0; it < 8; it++) {
            int r = it * 16 + rr;
            cp16(as + (uint32_t)(r * HSTR + f_ * 8) * 2u, A + (size_t)r * lda + k0 + f_ * 8);
            cp16(bs + (uint32_t)(r * HSTR + f_ * 8) * 2u, B + (size_t)r * ldb + k0 + f_ * 8);
        }
    };

    issue(0); CP_COMMIT();

    for (int ci = 0; ci < nch; ci++) {
        if (ci + 1 < nch) { issue(ci + 1); CP_COMMIT(); CP_WAIT1(); }
        else              { CP_WAIT0(); }
        __syncthreads();

        uint32_t As = smb + (uint32_t)((ci & 1) * STAGE_H) * 2u;
        uint32_t Bs = As + (uint32_t)TILE_H * 2u;
        uint32_t aBase = As + (uint32_t)(wm * 64) * HSTRB + ldA;
        uint32_t bBase = Bs + (uint32_t)(wn * 64) * HSTRB + ldB;

        uint32_t a[2][4][4], b[2][8][2];
        // prime ks=0
#pragma unroll
        for (int mt = 0; mt < 4; mt++)
            LDSM4(a[0][mt][0], a[0][mt][1], a[0][mt][2], a[0][mt][3],
                  aBase + (uint32_t)(mt * 16) * HSTRB);
#pragma unroll
        for (int np = 0; np < 4; np++)
            LDSM4(b[0][2*np][0], b[0][2*np][1], b[0][2*np+1][0], b[0][2*np+1][1],
                  bBase + (uint32_t)(np * 16) * HSTRB);

#pragma unroll
        for (int ks = 0; ks < 4; ks++) {
            int cur = ks & 1, nxt = cur ^ 1;
            if (ks < 3) {
                uint32_t ko = (uint32_t)((ks + 1) * 32);   // 16 halves = 32 B
#pragma unroll
                for (int mt = 0; mt < 4; mt++)
                    LDSM4(a[nxt][mt][0], a[nxt][mt][1], a[nxt][mt][2], a[nxt][mt][3],
                          aBase + (uint32_t)(mt * 16) * HSTRB + ko);
#pragma unroll
                for (int np = 0; np < 4; np++)
                    LDSM4(b[nxt][2*np][0], b[nxt][2*np][1], b[nxt][2*np+1][0], b[nxt][2*np+1][1],
                          bBase + (uint32_t)(np * 16) * HSTRB + ko);
            }
#pragma unroll
            for (int mt = 0; mt < 4; mt++)
#pragma unroll
                for (int nt = 0; nt < 8; nt++)
                    MMAH(acc[mt][nt], a[cur][mt], b[cur][nt]);
        }
        __syncthreads();
    }

    // Stage D through smem (fp32 view): Ds[col][row], stride 133
    float* Ds = (float*)hsm;
#pragma unroll
    for (int mt = 0; mt < 4; mt++)
#pragma unroll
        for (int nt = 0; nt < 8; nt++) {
            int r = wm * 64 + mt * 16 + g;
            int c = wn * 64 + nt * 8 + 2 * t;
            Ds[c * 133 + r]           = acc[mt][nt][0];
            Ds[(c + 1) * 133 + r]     = acc[mt][nt][1];
            Ds[c * 133 + r + 8]       = acc[mt][nt][2];
            Ds[(c + 1) * 133 + r + 8] = acc[mt][nt][3];
        }
    __syncthreads();

    if (MODE == 0) {
        if (n0 < 1024) {   // Q (scaled by ATT_SCALE*log2e) / K -> g_qkh
            float sc = (n0 < 512) ? QSC_L2E : 1.f;
#pragma unroll 8
            for (int p = 0; p < 128; p++) {
                int e = p * 128 + tid; int r = e >> 7; int c = e & 127;
                g_qkh[((size_t)z * NSP + m0 + r) * 1024 + n0 + c] =
                    __float2half_rn((Ds[c * 133 + r] + bias[n0 + c]) * sc);
            }
        } else {           // V transposed -> g_vth fp16 [b,h][d][m]
            int h = (n0 - 1024) >> 7;
#pragma unroll 8
            for (int p = 0; p < 128; p++) {
                int e = p * 128 + tid; int c = e >> 7; int r = e & 127;
                g_vth[(((size_t)z * HEADS + h) * HD + c) * NSP + m0 + r] =
                    __float2half_rn(Ds[c * 133 + r] + bias[n0 + c]);
            }
        }
    } else {               // MODE 3: bias + residual, transposed -> out fp32
#pragma unroll 8
        for (int p = 0; p < 128; p++) {
            int e = p * 128 + tid; int c = e >> 7; int r = e & 127;
            size_t off = ((size_t)z * CH + n0 + c) * NSP + m0 + r;
            outp[off] = Ds[c * 133 + r] + bias[n0 + c] + resid[off];
        }
    }
}

// ---------------------------------------------------------------------------
// Fused flash attention, fp16 mma + ldmatrix. CTA = 128 thr (4 warps),
// q-tile 64; each warp owns 16 q-rows; Q fragments persistent in registers.
// Streams 16 k-tiles of 64 keys.
// smem (halves): bufQ 64x136 @0, bufK 64x136 @8704, bufV 128x72 @17408.
// Scores in log2 domain (scale*log2e folded into Q) -> exp2f softmax.
// fp16 C-layout == A-layout: P feeds PV via register packs.
// grid = (NSP/64, BATCH*HEADS)
// ---------------------------------------------------------------------------
#define FLH_SMEM 53248
#define QKSTRB 272     // 136 halves
#define VSTRB  144     // 72 halves

__global__ __launch_bounds__(128, 3) void flash_kernel()
{
    extern __shared__ __half hsm[];
    const int tid = threadIdx.x;
    uint32_t smb = smem_u32(hsm);
    const uint32_t kOff = 8704u * 2u, vOff = 17408u * 2u;
    const int lane = tid & 31, wid = tid >> 5;
    const int g = lane >> 2, t = lane & 3;

    // ldmatrix per-lane byte offsets
    const uint32_t ldQ = (uint32_t)(((lane & 7) + ((lane >> 3) & 1) * 8) * QKSTRB + (lane >> 4) * 16);
    const uint32_t ldK = (uint32_t)((lane & 7) * QKSTRB + (lane >> 3) * 16);
    const uint32_t ldV = (uint32_t)((lane & 7) * VSTRB  + (lane >> 3) * 16);

    int n0 = blockIdx.x * 64;
    int bh = blockIdx.y;
    int b = bh >> 2, h = bh & 3;
    const __half* qh = g_qkh + (size_t)b * NSP * 1024 + h * HD;
    const __half* kh = qh + 512;
    const __half* vh = g_vth + (size_t)bh * HD * NSP;

    // Stage Q -> bufQ, K_0 -> bufK (each 64 rows x 128 halves, 1024 chunks)
#pragma unroll
    for (int tr = 0; tr < 8; tr++) {
        int id = tr * 128 + tid; int r = id >> 4, f = id & 15;
        cp16(smb + (uint32_t)(r * 136 + f * 8) * 2u, qh + (size_t)(n0 + r) * 1024 + f * 8);
        cp16(smb + kOff + (uint32_t)(r * 136 + f * 8) * 2u, kh + (size_t)r * 1024 + f * 8);
    }
    CP_COMMIT();
    CP_WAIT0();
    __syncthreads();

    // Q fragments: 8 k16-steps, one ldmatrix.x4 each; persistent
    uint32_t qf[8][4];
    {
        uint32_t qBase = smb + (uint32_t)(wid * 16) * QKSTRB + ldQ;
#pragma unroll
        for (int ks = 0; ks < 8; ks++)
            LDSM4(qf[ks][0], qf[ks][1], qf[ks][2], qf[ks][3], qBase + ks * 32);
    }

    float oacc[16][4];
#pragma unroll
    for (int i = 0; i < 16; i++)
#pragma unroll
        for (int q = 0; q < 4; q++) oacc[i][q] = 0.f;
    float rowm[2] = {-1e30f, -1e30f};
    float rowl[2] = {0.f, 0.f};

    for (int it = 0; it < 16; it++) {
        CP_WAIT0();      // K_it resident
        __syncthreads();

        // prefetch V_it -> bufV: 128 d-rows x 64 halves = 1024 chunks
#pragma unroll
        for (int tr = 0; tr < 8; tr++) {
            int id = tr * 128 + tid; int d = id >> 3, f = id & 7;
            cp16(smb + vOff + (uint32_t)(d * 72 + f * 8) * 2u,
                 vh + (size_t)d * NSP + it * 64 + f * 8);
        }
        CP_COMMIT();

        // S = Q K^T : per nt, 4 ldmatrix.x4 (each covers 2 k16 steps)
        float sacc[8][4];
#pragma unroll
        for (int i = 0; i < 8; i++)
#pragma unroll
            for (int q = 0; q < 4; q++) sacc[i][q] = 0.f;

#pragma unroll
        for (int nt = 0; nt < 8; nt++) {
            uint32_t kaddr = smb + kOff + (uint32_t)(nt * 8) * QKSTRB + ldK;
#pragma unroll
            for (int kp = 0; kp < 4; kp++) {
                uint32_t b0, b1, b2, b3;
                LDSM4(b0, b1, b2, b3, kaddr + kp * 64);
                uint32_t bb0[2] = {b0, b1}, bb1[2] = {b2, b3};
                MMAH(sacc[nt], qf[2 * kp],     bb0);
                MMAH(sacc[nt], qf[2 * kp + 1], bb1);
            }
        }

        // online softmax, log2 domain (scale*log2e already in Q)
        float tm0 = -1e30f, tm1 = -1e30f;
#pragma unroll
        for (int nt = 0; nt < 8; nt++) {
            tm0 = fmaxf(tm0, fmaxf(sacc[nt][0], sacc[nt][1]));
            tm1 = fmaxf(tm1, fmaxf(sacc[nt][2], sacc[nt][3]));
        }
#pragma unroll
        for (int o = 1; o < 4; o <<= 1) {
            tm0 = fmaxf(tm0, __shfl_xor_sync(0xffffffffu, tm0, o));
            tm1 = fmaxf(tm1, __shfl_xor_sync(0xffffffffu, tm1, o));
        }
        float mn0 = fmaxf(rowm[0], tm0), mn1 = fmaxf(rowm[1], tm1);
        float al0 = exp2f(rowm[0] - mn0), al1 = exp2f(rowm[1] - mn1);
        float ts0 = 0.f, ts1 = 0.f;
#pragma unroll
        for (int nt = 0; nt < 8; nt++) {
            sacc[nt][0] = exp2f(sacc[nt][0] - mn0);
            sacc[nt][1] = exp2f(sacc[nt][1] - mn0);
            sacc[nt][2] = exp2f(sacc[nt][2] - mn1);
            sacc[nt][3] = exp2f(sacc[nt][3] - mn1);
            ts0 += sacc[nt][0] + sacc[nt][1];
            ts1 += sacc[nt][2] + sacc[nt][3];
        }
#pragma unroll
        for (int o = 1; o < 4; o <<= 1) {
            ts0 += __shfl_xor_sync(0xffffffffu, ts0, o);
            ts1 += __shfl_xor_sync(0xffffffffu, ts1, o);
        }
        rowl[0] = rowl[0] * al0 + ts0;
        rowl[1] = rowl[1] * al1 + ts1;
        rowm[0] = mn0; rowm[1] = mn1;
#pragma unroll
        for (int nt = 0; nt < 16; nt++) {
            oacc[nt][0] *= al0; oacc[nt][1] *= al0;
            oacc[nt][2] *= al1; oacc[nt][3] *= al1;
        }

        CP_WAIT0();      // V_it resident
        __syncthreads(); // all warps done reading bufK

        if (it < 15) {   // prefetch K_{it+1} -> bufK
            const __half* kb = kh + (size_t)(it + 1) * 64 * 1024;
#pragma unroll
            for (int tr = 0; tr < 8; tr++) {
                int id = tr * 128 + tid; int r = id >> 4, f = id & 15;
                cp16(smb + kOff + (uint32_t)(r * 136 + f * 8) * 2u, kb + (size_t)r * 1024 + f * 8);
            }
            CP_COMMIT();
        }

        // O += P V^T : per kp (2 kt steps), pack P; per nt one ldmatrix.x4
#pragma unroll
        for (int kp = 0; kp < 2; kp++) {
            uint32_t pa0[4], pa1[4];
            int k0 = 2 * kp, k1 = 2 * kp + 1;
            pa0[0] = packh2(sacc[2*k0][0],   sacc[2*k0][1]);
            pa0[1] = packh2(sacc[2*k0][2],   sacc[2*k0][3]);
            pa0[2] = packh2(sacc[2*k0+1][0], sacc[2*k0+1][1]);
            pa0[3] = packh2(sacc[2*k0+1][2], sacc[2*k0+1][3]);
            pa1[0] = packh2(sacc[2*k1][0],   sacc[2*k1][1]);
            pa1[1] = packh2(sacc[2*k1][2],   sacc[2*k1][3]);
            pa1[2] = packh2(sacc[2*k1+1][0], sacc[2*k1+1][1]);
            pa1[3] = packh2(sacc[2*k1+1][2], sacc[2*k1+1][3]);
#pragma unroll
            for (int nt = 0; nt < 16; nt++) {
                uint32_t vaddr = smb + vOff + (uint32_t)(nt * 8) * VSTRB + ldV + kp * 64;
                uint32_t b0, b1, b2, b3;
                LDSM4(b0, b1, b2, b3, vaddr);
                uint32_t bb0[2] = {b0, b1}, bb1[2] = {b2, b3};
                MMAH(oacc[nt], pa0, bb0);
                MMAH(oacc[nt], pa1, bb1);
            }
        }
    }

    // normalize + direct fp16 stores -> g_oth[b][n][c]
    float inv0 = 1.f / rowl[0], inv1 = 1.f / rowl[1];
    int r = wid * 16 + g;
    __half* ob = g_oth + ((size_t)b * NSP + n0) * CH + h * HD;
#pragma unroll
    for (int nt = 0; nt < 16; nt++) {
        int d = nt * 8 + 2 * t;
        *(uint32_t*)&ob[(size_t)r * CH + d] =
            packh2(oacc[nt][0] * inv0, oacc[nt][1] * inv0);
        *(uint32_t*)&ob[(size_t)(r + 8) * CH + d] =
            packh2(oacc[nt][2] * inv1, oacc[nt][3] * inv1);
    }
}

// ---------------------------------------------------------------------------
// Launch
// ---------------------------------------------------------------------------
extern "C" void kernel_launch(void* const* d_in, const int* in_sizes, int n_in,
                              void* d_out, int out_size)
{
    const float* x      = (const float*)d_in[0];
    const float* norm_w = (const float*)d_in[1];
    const float* norm_b = (const float*)d_in[2];
    const float* qkv_w  = (const float*)d_in[3];
    const float* qkv_b  = (const float*)d_in[4];
    const float* proj_w = (const float*)d_in[5];
    const float* proj_b = (const float*)d_in[6];
    float* out = (float*)d_out;

    cudaFuncSetAttribute(gemm_tc<0>, cudaFuncAttributeMaxDynamicSharedMemorySize, GEMM_SMEM);
    cudaFuncSetAttribute(gemm_tc<3>, cudaFuncAttributeMaxDynamicSharedMemorySize, GEMM_SMEM);
    cudaFuncSetAttribute(flash_kernel, cudaFuncAttributeMaxDynamicSharedMemorySize, FLH_SMEM);

    cvtw_kernel<<<(3 * CH * CH + 255) / 256, 256>>>(qkv_w, proj_w);
    gn_kernel<<<BATCH * GROUPS_N, 256>>>(x, norm_w, norm_b);

    gemm_tc<0><<<dim3(NSP / 128, 1536 / 128, BATCH), 128, GEMM_SMEM>>>(qkv_b, nullptr, nullptr);
    flash_kernel<<<dim3(NSP / 64, BATCH * HEADS), 128, FLH_SMEM>>>();
    gemm_tc<3><<<dim3(NSP / 128, CH / 128, BATCH), 128, GEMM_SMEM>>>(proj_b, x, out);
}